// round 13
// baseline (speedup 1.0000x reference)
#include <cuda_runtime.h>
#include <cuda_fp16.h>
#include <cstdint>

#define MAXN 50000
#define MAXE 800000
#define DIM  128
#define NGRAPH 64
#define SCAN_BLK 512
#define MAXB ((MAXN + SCAN_BLK - 1) / SCAN_BLK)   // 98
#define NODE_W 4                                   // per-node constant weight

typedef unsigned long long ull;

// ---- static scratch (device globals: allocation-free) ----
__device__ int    d_deg[MAXN];
__device__ int    d_rank[MAXE];
__device__ float  d_dinv[MAXN];
__device__ int    d_offsets[MAXN + 1];
__device__ int    d_bsum[MAXB + 1];
__device__ int    d_boff[MAXB + 1];
__device__ ull    d_csr[MAXE];                    // packed (src:int32, norm:f32)
__device__ __half d_hwh[(size_t)MAXN * DIM];      // GEMM output, fp16 (both layers)
__device__ __half d_x1h[(size_t)MAXN * DIM];      // layer-1 activations, fp16

// ---- f32x2 packed helpers (Blackwell sm_100a) ----
__device__ __forceinline__ void ffma2(ull& d, ull a, ull b) {
    asm("fma.rn.f32x2 %0, %1, %2, %0;" : "+l"(d) : "l"(a), "l"(b));
}
__device__ __forceinline__ ull pack2(float lo, float hi) {
    ull r; asm("mov.b64 %0, {%1, %2};" : "=l"(r) : "f"(lo), "f"(hi)); return r;
}
__device__ __forceinline__ float sum2(ull v) {
    float lo, hi; asm("mov.b64 {%0, %1}, %2;" : "=f"(lo), "=f"(hi) : "l"(v));
    return lo + hi;
}

// ---------------------------------------------------------------------------
__global__ void init_k(float* __restrict__ pool, int N) {
    int i = blockIdx.x * blockDim.x + threadIdx.x;
    if (i < N) d_deg[i] = 1;
    if (i < NGRAPH * 2 * DIM) pool[i] = 0.0f;
}

__global__ void count_k(const int* __restrict__ ei, int E, int N) {
    int e = blockIdx.x * blockDim.x + threadIdx.x;
    if (e < E) {
        int d = ei[E + e];
        int r = 0;
        if ((unsigned)d < (unsigned)N) r = atomicAdd(&d_deg[d], 1) - 1;
        d_rank[e] = r;
    }
}

// ---------------------------------------------------------------------------
// 3-phase multi-block exclusive scan of (deg-1); also writes dinv.
// ---------------------------------------------------------------------------
__global__ void scan1_k(int N) {
    __shared__ int sm[SCAN_BLK];
    int i = blockIdx.x * SCAN_BLK + threadIdx.x;
    int v = 0;
    if (i < N) {
        int dg = d_deg[i];
        v = dg - 1;
        d_dinv[i] = rsqrtf((float)dg);
    }
    sm[threadIdx.x] = v;
    __syncthreads();
    for (int off = 1; off < SCAN_BLK; off <<= 1) {
        int t = (threadIdx.x >= off) ? sm[threadIdx.x - off] : 0;
        __syncthreads();
        sm[threadIdx.x] += t;
        __syncthreads();
    }
    if (i < N) d_offsets[i] = sm[threadIdx.x] - v;
    if (threadIdx.x == SCAN_BLK - 1) d_bsum[blockIdx.x] = sm[SCAN_BLK - 1];
}

__global__ void scan2_k(int nb) {
    __shared__ int sm[128];
    int t = threadIdx.x;
    int v = (t < nb) ? d_bsum[t] : 0;
    sm[t] = v;
    __syncthreads();
    for (int off = 1; off < 128; off <<= 1) {
        int u = (t >= off) ? sm[t - off] : 0;
        __syncthreads();
        sm[t] += u;
        __syncthreads();
    }
    if (t < nb) d_boff[t] = sm[t] - v;
    if (t == nb - 1) d_boff[nb] = sm[t];
}

__global__ void scan3_k(int N, int nb) {
    int i = blockIdx.x * SCAN_BLK + threadIdx.x;
    if (i < N) d_offsets[i] += d_boff[blockIdx.x];
    if (i == 0) d_offsets[N] = d_boff[nb];
}

// ---------------------------------------------------------------------------
__global__ void fill_k(const int* __restrict__ ei, int E, int N) {
    int e = blockIdx.x * blockDim.x + threadIdx.x;
    if (e >= E) return;
    int s = ei[e];
    int d = ei[E + e];
    if ((unsigned)s >= (unsigned)N || (unsigned)d >= (unsigned)N) return;
    int p = d_offsets[d] + d_rank[e];
    if ((unsigned)p < (unsigned)E) {
        float nrm = d_dinv[s] * d_dinv[d];
        d_csr[p] = (ull)(unsigned)s | ((ull)__float_as_uint(nrm) << 32);
    }
}

// ---------------------------------------------------------------------------
// GEMM: d_hwh[N,128](fp16) = src @ W, fp32 math via fma.f32x2.
// LAYER 0 src = fp32 input x; LAYER 1 src = fp16 d_x1h (converted at Xs fill).
// Two 32-row tiles per block under one W load. grid=(ceil(N/64),2), 128 thr.
// ---------------------------------------------------------------------------
template <int LAYER>
__global__ void __launch_bounds__(128) gemm_k(const float* __restrict__ A,
                                              const float* __restrict__ Wg, int N) {
    __shared__ ull Ws[64 * 64];                    // 32 KB
    __shared__ __align__(16) ull Xs[32 * 64];      // 16 KB

    int c0 = blockIdx.y * 64;
    for (int i = threadIdx.x; i < 64 * 64; i += 128) {
        int k2 = i >> 6, c = i & 63;
        float lo = Wg[(size_t)(2 * k2) * 128 + c0 + c];
        float hi = Wg[(size_t)(2 * k2 + 1) * 128 + c0 + c];
        Ws[i] = pack2(lo, hi);
    }

    int warp = threadIdx.x >> 5, lane = threadIdx.x & 31;
    int rr0 = warp * 8;

#pragma unroll 1
    for (int tile = 0; tile < 2; tile++) {
        int r0 = blockIdx.x * 64 + tile * 32;
        int rows = N - r0; if (rows > 32) rows = 32;
        if (rows <= 0) { __syncthreads(); __syncthreads(); continue; }

        if (LAYER == 0) {
            const ull* src2 = (const ull*)(A + (size_t)r0 * 128);
            for (int i = threadIdx.x; i < rows * 64; i += 128)
                Xs[i] = src2[i];
        } else {
            const unsigned* srch = (const unsigned*)(d_x1h + (size_t)r0 * 128);
            for (int i = threadIdx.x; i < rows * 64; i += 128) {
                float2 f = __half22float2(*(const __half2*)&srch[i]);
                Xs[i] = pack2(f.x, f.y);
            }
        }
        __syncthreads();

        ull acc[8][2];
#pragma unroll
        for (int r = 0; r < 8; r++) { acc[r][0] = 0ull; acc[r][1] = 0ull; }

#pragma unroll 8
        for (int k2 = 0; k2 < 64; k2 += 2) {
            ull w00 = Ws[k2 * 64 + lane];
            ull w01 = Ws[k2 * 64 + 32 + lane];
            ull w10 = Ws[(k2 + 1) * 64 + lane];
            ull w11 = Ws[(k2 + 1) * 64 + 32 + lane];
#pragma unroll
            for (int r = 0; r < 8; r++) {
                ulonglong2 xv = *(const ulonglong2*)&Xs[(rr0 + r) * 64 + k2];
                ffma2(acc[r][0], xv.x, w00);
                ffma2(acc[r][1], xv.x, w01);
                ffma2(acc[r][0], xv.y, w10);
                ffma2(acc[r][1], xv.y, w11);
            }
        }

#pragma unroll
        for (int r = 0; r < 8; r++) {
            int row = r0 + rr0 + r;
            if (row < N) {
                d_hwh[(size_t)row * 128 + c0 + lane]      = __float2half_rn(sum2(acc[r][0]));
                d_hwh[(size_t)row * 128 + c0 + 32 + lane] = __float2half_rn(sum2(acc[r][1]));
            }
        }
        __syncthreads();
    }
}

// ---------------------------------------------------------------------------
// Aggregation + ReLU + fused max-pool, EDGE-BALANCED warp ranges.
// Weight key: key(i) = offsets[i] + NODE_W*i (monotone; searched in-place).
// ---------------------------------------------------------------------------
__device__ __forceinline__ void pool_flush(float* pool, int g, int pool_off,
                                           int lane, float4 m) {
    unsigned* p = (unsigned*)(pool + (size_t)g * (2 * DIM) + pool_off + lane * 4);
    atomicMax(p + 0, __float_as_uint(m.x));
    atomicMax(p + 1, __float_as_uint(m.y));
    atomicMax(p + 2, __float_as_uint(m.z));
    atomicMax(p + 3, __float_as_uint(m.w));
}

__device__ __forceinline__ void fma_h4(float4& acc, uint2 u, float n) {
    float2 a = __half22float2(*(__half2*)&u.x);
    float2 b = __half22float2(*(__half2*)&u.y);
    acc.x = fmaf(n, a.x, acc.x); acc.y = fmaf(n, a.y, acc.y);
    acc.z = fmaf(n, b.x, acc.z); acc.w = fmaf(n, b.y, acc.w);
}

__device__ __forceinline__ int find_split(long long t, int N) {
    // smallest i in [0,N] with offsets[i+1] + NODE_W*(i+1) > t  (i==N if none)
    int lo = 0, hi = N;
    while (lo < hi) {
        int mid = (lo + hi) >> 1;
        long long key = (long long)d_offsets[mid + 1] + (long long)NODE_W * (mid + 1);
        if (key > t) hi = mid; else lo = mid + 1;
    }
    return lo;
}

template <int LAYER>
__global__ void __launch_bounds__(256) agg_k(const int* __restrict__ batch,
                                             float* __restrict__ pool, int N) {
    int warp = threadIdx.x >> 5, lane = threadIdx.x & 31;
    int gw = blockIdx.x * (blockDim.x >> 5) + warp;
    int W = gridDim.x * (blockDim.x >> 5);

    long long total = (long long)d_offsets[N] + (long long)NODE_W * N;
    long long t0 = total * gw / W;
    long long t1 = total * (gw + 1) / W;
    int i0 = find_split(t0, N);
    int i1 = find_split(t1, N);
    if (i0 >= i1) return;

    const uint2* hwh = (const uint2*)d_hwh;     // 8B = 4 halves per lane
    float4 rmax = make_float4(0.f, 0.f, 0.f, 0.f);
    int curg = -1;
    const int pool_off = (LAYER == 0) ? 0 : DIM;

    for (int i = i0; i < i1; i++) {
        float di = d_dinv[i];
        float sl = di * di;
        float4 acc = make_float4(0.f, 0.f, 0.f, 0.f);
        fma_h4(acc, hwh[(size_t)i * 32 + lane], sl);

        int s = d_offsets[i], e = d_offsets[i + 1];
        int j = s;

        for (; j + 8 <= e; j += 8) {
            ull pk[8];
#pragma unroll
            for (int t = 0; t < 8; t++) pk[t] = d_csr[j + t];
            uint2 v[8];
#pragma unroll
            for (int t = 0; t < 8; t++)
                v[t] = hwh[(size_t)(unsigned)(int)pk[t] * 32 + lane];
#pragma unroll
            for (int t = 0; t < 8; t++)
                fma_h4(acc, v[t], __uint_as_float((unsigned)(pk[t] >> 32)));
        }
        if (j + 4 <= e) {
            ull pk[4];
#pragma unroll
            for (int t = 0; t < 4; t++) pk[t] = d_csr[j + t];
            uint2 v[4];
#pragma unroll
            for (int t = 0; t < 4; t++)
                v[t] = hwh[(size_t)(unsigned)(int)pk[t] * 32 + lane];
#pragma unroll
            for (int t = 0; t < 4; t++)
                fma_h4(acc, v[t], __uint_as_float((unsigned)(pk[t] >> 32)));
            j += 4;
        }
        for (; j < e; j++) {
            ull pk = d_csr[j];
            uint2 v = hwh[(size_t)(unsigned)(int)pk * 32 + lane];
            fma_h4(acc, v, __uint_as_float((unsigned)(pk >> 32)));
        }

        acc.x = fmaxf(acc.x, 0.f); acc.y = fmaxf(acc.y, 0.f);
        acc.z = fmaxf(acc.z, 0.f); acc.w = fmaxf(acc.w, 0.f);

        if (LAYER == 0) {
            uint2 h;
            *(__half2*)&h.x = __floats2half2_rn(acc.x, acc.y);
            *(__half2*)&h.y = __floats2half2_rn(acc.z, acc.w);
            ((uint2*)d_x1h)[(size_t)i * 32 + lane] = h;
        }

        int g = batch[i];
        if ((unsigned)g >= (unsigned)NGRAPH) g = 0;   // guard
        if (g != curg) {
            if (curg >= 0) pool_flush(pool, curg, pool_off, lane, rmax);
            curg = g;
            rmax = acc;
        } else {
            rmax.x = fmaxf(rmax.x, acc.x); rmax.y = fmaxf(rmax.y, acc.y);
            rmax.z = fmaxf(rmax.z, acc.z); rmax.w = fmaxf(rmax.w, acc.w);
        }
    }
    if (curg >= 0) pool_flush(pool, curg, pool_off, lane, rmax);
}

// ---------------------------------------------------------------------------
extern "C" void kernel_launch(void* const* d_in, const int* in_sizes, int n_in,
                              void* d_out, int out_size) {
    const float* x     = (const float*)d_in[0];
    const int*   ei    = (const int*)d_in[1];     // int64 inputs delivered as int32
    const int*   batch = (const int*)d_in[2];
    const float* W1    = (const float*)d_in[3];
    const float* W2    = (const float*)d_in[4];
    float* out = (float*)d_out;

    int N = in_sizes[2];       // 50000
    int E = in_sizes[1] / 2;   // 800000
    int nb = (N + SCAN_BLK - 1) / SCAN_BLK;

    static cudaStream_t s1 = [] {
        cudaStream_t s; cudaStreamCreateWithFlags(&s, cudaStreamNonBlocking); return s;
    }();
    static cudaEvent_t evFork = [] {
        cudaEvent_t e; cudaEventCreateWithFlags(&e, cudaEventDisableTiming); return e;
    }();
    static cudaEvent_t evG0 = [] {
        cudaEvent_t e; cudaEventCreateWithFlags(&e, cudaEventDisableTiming); return e;
    }();

    int gemmBlocks = (N + 63) / 64;
    int aggWarps   = (N + 7) / 8;
    int aggBlocks  = (aggWarps + 7) / 8;

    // --- fork: gemm0 concurrent with the CSR build ---
    cudaEventRecord(evFork, 0);
    cudaStreamWaitEvent(s1, evFork, 0);
    gemm_k<0><<<dim3(gemmBlocks, 2), 128, 0, s1>>>(x, W1, N);
    cudaEventRecord(evG0, s1);

    // --- setup chain on the main stream ---
    int initN = N > NGRAPH * 2 * DIM ? N : NGRAPH * 2 * DIM;
    init_k<<<(initN + 255) / 256, 256>>>(out, N);
    count_k<<<(E + 255) / 256, 256>>>(ei, E, N);
    scan1_k<<<nb, SCAN_BLK>>>(N);
    scan2_k<<<1, 128>>>(nb);
    scan3_k<<<nb, SCAN_BLK>>>(N, nb);
    fill_k<<<(E + 255) / 256, 256>>>(ei, E, N);

    // --- join, then serial core ---
    cudaStreamWaitEvent(0, evG0, 0);
    agg_k<0><<<aggBlocks, 256>>>(batch, out, N);
    gemm_k<1><<<dim3(gemmBlocks, 2), 128>>>(nullptr, W2, N);
    agg_k<1><<<aggBlocks, 256>>>(batch, out, N);
}

// round 15
// speedup vs baseline: 1.0705x; 1.0705x over previous
#include <cuda_runtime.h>
#include <cuda_fp16.h>
#include <cstdint>

#define MAXN 50000
#define MAXE 800000
#define DIM  128
#define NGRAPH 64
#define SCAN_BLK 512
#define SCAN_SHIFT 9
#define MAXB ((MAXN + SCAN_BLK - 1) / SCAN_BLK)   // 98

typedef unsigned long long ull;

// ---- static scratch (device globals: allocation-free) ----
__device__ int    d_deg[MAXN];
__device__ int    d_rank[MAXE];
__device__ float  d_dinv[MAXN];
__device__ int    d_offsets[MAXN + 1];            // BLOCK-LOCAL exclusive scans
__device__ int    d_bsum[MAXB + 1];
__device__ int    d_boff[MAXB + 1];               // block offsets; [nb] = total
__device__ ull    d_csr[MAXE];                    // packed (src:int32, norm:f32)
__device__ __half d_hwh[(size_t)MAXN * DIM];      // GEMM output, fp16 (both layers)
__device__ float  d_x1[(size_t)MAXN * DIM];       // layer-1 activations (fp32)

// ---- f32x2 packed helpers (Blackwell sm_100a) ----
__device__ __forceinline__ void ffma2(ull& d, ull a, ull b) {
    asm("fma.rn.f32x2 %0, %1, %2, %0;" : "+l"(d) : "l"(a), "l"(b));
}
__device__ __forceinline__ ull pack2(float lo, float hi) {
    ull r; asm("mov.b64 %0, {%1, %2};" : "=l"(r) : "f"(lo), "f"(hi)); return r;
}
__device__ __forceinline__ float sum2(ull v) {
    float lo, hi; asm("mov.b64 {%0, %1}, %2;" : "=f"(lo), "=f"(hi) : "l"(v));
    return lo + hi;
}

// ---------------------------------------------------------------------------
__global__ void init_k(float* __restrict__ pool, int N) {
    int i = blockIdx.x * blockDim.x + threadIdx.x;
    if (i < N) d_deg[i] = 1;
    if (i < NGRAPH * 2 * DIM) pool[i] = 0.0f;
}

__global__ void count_k(const int* __restrict__ ei, int E, int N) {
    int e = blockIdx.x * blockDim.x + threadIdx.x;
    if (e < E) {
        int d = ei[E + e];
        int r = 0;
        if ((unsigned)d < (unsigned)N) r = atomicAdd(&d_deg[d], 1) - 1;
        d_rank[e] = r;
    }
}

// ---------------------------------------------------------------------------
// 2-phase scan: block-local exclusive scans + block-sum scan. No add-back
// pass: consumers reconstruct global = local + d_boff[i >> SCAN_SHIFT].
// ---------------------------------------------------------------------------
__global__ void scan1_k(int N) {
    __shared__ int sm[SCAN_BLK];
    int i = blockIdx.x * SCAN_BLK + threadIdx.x;
    int v = 0;
    if (i < N) {
        int dg = d_deg[i];
        v = dg - 1;
        d_dinv[i] = rsqrtf((float)dg);
    }
    sm[threadIdx.x] = v;
    __syncthreads();
    for (int off = 1; off < SCAN_BLK; off <<= 1) {
        int t = (threadIdx.x >= off) ? sm[threadIdx.x - off] : 0;
        __syncthreads();
        sm[threadIdx.x] += t;
        __syncthreads();
    }
    if (i < N) d_offsets[i] = sm[threadIdx.x] - v;   // local exclusive
    if (threadIdx.x == SCAN_BLK - 1) d_bsum[blockIdx.x] = sm[SCAN_BLK - 1];
}

__global__ void scan2_k(int nb) {
    __shared__ int sm[128];
    int t = threadIdx.x;
    int v = (t < nb) ? d_bsum[t] : 0;
    sm[t] = v;
    __syncthreads();
    for (int off = 1; off < 128; off <<= 1) {
        int u = (t >= off) ? sm[t - off] : 0;
        __syncthreads();
        sm[t] += u;
        __syncthreads();
    }
    if (t < nb) d_boff[t] = sm[t] - v;               // exclusive
    if (t == nb - 1) d_boff[nb] = sm[t];             // total
}

// ---------------------------------------------------------------------------
__global__ void fill_k(const int* __restrict__ ei, int E, int N) {
    int e = blockIdx.x * blockDim.x + threadIdx.x;
    if (e >= E) return;
    int s = ei[e];
    int d = ei[E + e];
    if ((unsigned)s >= (unsigned)N || (unsigned)d >= (unsigned)N) return;
    int p = d_offsets[d] + d_boff[d >> SCAN_SHIFT] + d_rank[e];
    if ((unsigned)p < (unsigned)E) {
        float nrm = d_dinv[s] * d_dinv[d];
        d_csr[p] = (ull)(unsigned)s | ((ull)__float_as_uint(nrm) << 32);
    }
}

// ---------------------------------------------------------------------------
// GEMM: d_hwh[N,128](fp16) = src[N,128] @ W[128,128], fp32 math via fma.f32x2.
// Two 32-row tiles per block under one W load. grid=(ceil(N/64),2), 128 thr.
// ---------------------------------------------------------------------------
template <int LAYER>
__global__ void __launch_bounds__(128) gemm_k(const float* __restrict__ A,
                                              const float* __restrict__ Wg, int N) {
    __shared__ ull Ws[64 * 64];                    // 32 KB
    __shared__ __align__(16) ull Xs[32 * 64];      // 16 KB

    int c0 = blockIdx.y * 64;
    for (int i = threadIdx.x; i < 64 * 64; i += 128) {
        int k2 = i >> 6, c = i & 63;
        float lo = Wg[(size_t)(2 * k2) * 128 + c0 + c];
        float hi = Wg[(size_t)(2 * k2 + 1) * 128 + c0 + c];
        Ws[i] = pack2(lo, hi);
    }

    const float* src = (LAYER == 0) ? A : (const float*)d_x1;
    int warp = threadIdx.x >> 5, lane = threadIdx.x & 31;
    int rr0 = warp * 8;

#pragma unroll 1
    for (int tile = 0; tile < 2; tile++) {
        int r0 = blockIdx.x * 64 + tile * 32;
        int rows = N - r0; if (rows > 32) rows = 32;
        if (rows <= 0) { __syncthreads(); __syncthreads(); continue; }

        const ull* src2 = (const ull*)(src + (size_t)r0 * 128);
        for (int i = threadIdx.x; i < rows * 64; i += 128)
            Xs[i] = src2[i];
        __syncthreads();

        ull acc[8][2];
#pragma unroll
        for (int r = 0; r < 8; r++) { acc[r][0] = 0ull; acc[r][1] = 0ull; }

#pragma unroll 8
        for (int k2 = 0; k2 < 64; k2 += 2) {
            ull w00 = Ws[k2 * 64 + lane];
            ull w01 = Ws[k2 * 64 + 32 + lane];
            ull w10 = Ws[(k2 + 1) * 64 + lane];
            ull w11 = Ws[(k2 + 1) * 64 + 32 + lane];
#pragma unroll
            for (int r = 0; r < 8; r++) {
                ulonglong2 xv = *(const ulonglong2*)&Xs[(rr0 + r) * 64 + k2];
                ffma2(acc[r][0], xv.x, w00);
                ffma2(acc[r][1], xv.x, w01);
                ffma2(acc[r][0], xv.y, w10);
                ffma2(acc[r][1], xv.y, w11);
            }
        }

#pragma unroll
        for (int r = 0; r < 8; r++) {
            int row = r0 + rr0 + r;
            if (row < N) {
                d_hwh[(size_t)row * 128 + c0 + lane]      = __float2half_rn(sum2(acc[r][0]));
                d_hwh[(size_t)row * 128 + c0 + 32 + lane] = __float2half_rn(sum2(acc[r][1]));
            }
        }
        __syncthreads();
    }
}

// ---------------------------------------------------------------------------
// Aggregation + ReLU + fused max-pool. Node-balanced warp ranges (R12 form).
// Offsets reconstructed from local scan + block offsets (L1-resident table).
// ---------------------------------------------------------------------------
__device__ __forceinline__ void pool_flush(float* pool, int g, int pool_off,
                                           int lane, float4 m) {
    unsigned* p = (unsigned*)(pool + (size_t)g * (2 * DIM) + pool_off + lane * 4);
    atomicMax(p + 0, __float_as_uint(m.x));
    atomicMax(p + 1, __float_as_uint(m.y));
    atomicMax(p + 2, __float_as_uint(m.z));
    atomicMax(p + 3, __float_as_uint(m.w));
}

__device__ __forceinline__ void fma_h4(float4& acc, uint2 u, float n) {
    float2 a = __half22float2(*(__half2*)&u.x);
    float2 b = __half22float2(*(__half2*)&u.y);
    acc.x = fmaf(n, a.x, acc.x); acc.y = fmaf(n, a.y, acc.y);
    acc.z = fmaf(n, b.x, acc.z); acc.w = fmaf(n, b.y, acc.w);
}

__device__ __forceinline__ int glob_off(int i, int N, int nb) {
    if (i >= N) return d_boff[nb];
    return d_offsets[i] + d_boff[i >> SCAN_SHIFT];
}

template <int LAYER>
__global__ void __launch_bounds__(256) agg_k(const int* __restrict__ batch,
                                             float* __restrict__ pool, int N, int nb) {
    int warp = threadIdx.x >> 5, lane = threadIdx.x & 31;
    int gw = blockIdx.x * (blockDim.x >> 5) + warp;
    int warpsTotal = gridDim.x * (blockDim.x >> 5);
    int npw = (N + warpsTotal - 1) / warpsTotal;
    int i0 = gw * npw;
    if (i0 >= N) return;
    int i1 = i0 + npw; if (i1 > N) i1 = N;

    const uint2* hwh = (const uint2*)d_hwh;     // 8B = 4 halves per lane
    float4 rmax = make_float4(0.f, 0.f, 0.f, 0.f);
    int curg = -1;
    const int pool_off = (LAYER == 0) ? 0 : DIM;

    int s = glob_off(i0, N, nb);
    for (int i = i0; i < i1; i++) {
        float di = d_dinv[i];
        float sl = di * di;
        float4 acc = make_float4(0.f, 0.f, 0.f, 0.f);
        fma_h4(acc, hwh[(size_t)i * 32 + lane], sl);

        int e = glob_off(i + 1, N, nb);
        int j = s;

        for (; j + 8 <= e; j += 8) {
            ull pk[8];
#pragma unroll
            for (int t = 0; t < 8; t++) pk[t] = d_csr[j + t];
            uint2 v[8];
#pragma unroll
            for (int t = 0; t < 8; t++)
                v[t] = hwh[(size_t)(unsigned)(int)pk[t] * 32 + lane];
#pragma unroll
            for (int t = 0; t < 8; t++)
                fma_h4(acc, v[t], __uint_as_float((unsigned)(pk[t] >> 32)));
        }
        if (j + 4 <= e) {
            ull pk[4];
#pragma unroll
            for (int t = 0; t < 4; t++) pk[t] = d_csr[j + t];
            uint2 v[4];
#pragma unroll
            for (int t = 0; t < 4; t++)
                v[t] = hwh[(size_t)(unsigned)(int)pk[t] * 32 + lane];
#pragma unroll
            for (int t = 0; t < 4; t++)
                fma_h4(acc, v[t], __uint_as_float((unsigned)(pk[t] >> 32)));
            j += 4;
        }
        for (; j < e; j++) {
            ull pk = d_csr[j];
            uint2 v = hwh[(size_t)(unsigned)(int)pk * 32 + lane];
            fma_h4(acc, v, __uint_as_float((unsigned)(pk >> 32)));
        }
        s = e;

        acc.x = fmaxf(acc.x, 0.f); acc.y = fmaxf(acc.y, 0.f);
        acc.z = fmaxf(acc.z, 0.f); acc.w = fmaxf(acc.w, 0.f);

        if (LAYER == 0)
            ((float4*)d_x1)[(size_t)i * 32 + lane] = acc;

        int g = batch[i];
        if ((unsigned)g >= (unsigned)NGRAPH) g = 0;   // guard
        if (g != curg) {
            if (curg >= 0) pool_flush(pool, curg, pool_off, lane, rmax);
            curg = g;
            rmax = acc;
        } else {
            rmax.x = fmaxf(rmax.x, acc.x); rmax.y = fmaxf(rmax.y, acc.y);
            rmax.z = fmaxf(rmax.z, acc.z); rmax.w = fmaxf(rmax.w, acc.w);
        }
    }
    if (curg >= 0) pool_flush(pool, curg, pool_off, lane, rmax);
}

// ---------------------------------------------------------------------------
extern "C" void kernel_launch(void* const* d_in, const int* in_sizes, int n_in,
                              void* d_out, int out_size) {
    const float* x     = (const float*)d_in[0];
    const int*   ei    = (const int*)d_in[1];     // int64 inputs delivered as int32
    const int*   batch = (const int*)d_in[2];
    const float* W1    = (const float*)d_in[3];
    const float* W2    = (const float*)d_in[4];
    float* out = (float*)d_out;

    int N = in_sizes[2];       // 50000
    int E = in_sizes[1] / 2;   // 800000
    int nb = (N + SCAN_BLK - 1) / SCAN_BLK;

    static cudaStream_t s1 = [] {
        cudaStream_t s; cudaStreamCreateWithFlags(&s, cudaStreamNonBlocking); return s;
    }();
    static cudaEvent_t evFork = [] {
        cudaEvent_t e; cudaEventCreateWithFlags(&e, cudaEventDisableTiming); return e;
    }();
    static cudaEvent_t evG0 = [] {
        cudaEvent_t e; cudaEventCreateWithFlags(&e, cudaEventDisableTiming); return e;
    }();

    int gemmBlocks = (N + 63) / 64;
    int aggWarps   = (N + 7) / 8;
    int aggBlocks  = (aggWarps + 7) / 8;

    // --- fork: gemm0 concurrent with the CSR build ---
    cudaEventRecord(evFork, 0);
    cudaStreamWaitEvent(s1, evFork, 0);
    gemm_k<0><<<dim3(gemmBlocks, 2), 128, 0, s1>>>(x, W1, N);
    cudaEventRecord(evG0, s1);

    // --- setup chain on the main stream (5 kernels; no add-back pass) ---
    int initN = N > NGRAPH * 2 * DIM ? N : NGRAPH * 2 * DIM;
    init_k<<<(initN + 255) / 256, 256>>>(out, N);
    count_k<<<(E + 255) / 256, 256>>>(ei, E, N);
    scan1_k<<<nb, SCAN_BLK>>>(N);
    scan2_k<<<1, 128>>>(nb);
    fill_k<<<(E + 255) / 256, 256>>>(ei, E, N);

    // --- join, then serial core ---
    cudaStreamWaitEvent(0, evG0, 0);
    agg_k<0><<<aggBlocks, 256>>>(batch, out, N, nb);
    gemm_k<1><<<dim3(gemmBlocks, 2), 128>>>(nullptr, W2, N);
    agg_k<1><<<aggBlocks, 256>>>(batch, out, N, nb);
}

// round 16
// speedup vs baseline: 1.3994x; 1.3073x over previous
#include <cuda_runtime.h>
#include <cuda_fp16.h>
#include <cstdint>

#define MAXN 50000
#define MAXE 800000
#define DIM  128
#define NGRAPH 64
#define SCAN_BLK 512
#define SCAN_SHIFT 9
#define MAXB ((MAXN + SCAN_BLK - 1) / SCAN_BLK)   // 98

typedef unsigned long long ull;

// ---- static scratch (device globals: allocation-free) ----
__device__ int    d_deg[MAXN];
__device__ int    d_rank[MAXE];
__device__ float  d_dinv[MAXN];
__device__ int    d_offsets[MAXN + 1];            // BLOCK-LOCAL exclusive scans
__device__ int    d_bsum[MAXB + 1];
__device__ int    d_boff[MAXB + 1];               // block offsets; [nb] = total
__device__ ull    d_csr[MAXE];                    // packed (src:int32, norm:f32)
__device__ __half d_hwh[(size_t)MAXN * DIM];      // GEMM output, fp16 (both layers)
__device__ float  d_x1[(size_t)MAXN * DIM];       // layer-1 activations (fp32)

// ---------------------------------------------------------------------------
__global__ void init_k(float* __restrict__ pool, int N) {
    int i = blockIdx.x * blockDim.x + threadIdx.x;
    if (i < N) d_deg[i] = 1;
    if (i < NGRAPH * 2 * DIM) pool[i] = 0.0f;
}

__global__ void count_k(const int* __restrict__ ei, int E, int N) {
    int e = blockIdx.x * blockDim.x + threadIdx.x;
    if (e < E) {
        int d = ei[E + e];
        int r = 0;
        if ((unsigned)d < (unsigned)N) r = atomicAdd(&d_deg[d], 1) - 1;
        d_rank[e] = r;
    }
}

// ---------------------------------------------------------------------------
// 2-phase scan: block-local exclusive scans + block-sum scan. No add-back
// pass: consumers reconstruct global = local + d_boff[i >> SCAN_SHIFT].
// ---------------------------------------------------------------------------
__global__ void scan1_k(int N) {
    __shared__ int sm[SCAN_BLK];
    int i = blockIdx.x * SCAN_BLK + threadIdx.x;
    int v = 0;
    if (i < N) {
        int dg = d_deg[i];
        v = dg - 1;
        d_dinv[i] = rsqrtf((float)dg);
    }
    sm[threadIdx.x] = v;
    __syncthreads();
    for (int off = 1; off < SCAN_BLK; off <<= 1) {
        int t = (threadIdx.x >= off) ? sm[threadIdx.x - off] : 0;
        __syncthreads();
        sm[threadIdx.x] += t;
        __syncthreads();
    }
    if (i < N) d_offsets[i] = sm[threadIdx.x] - v;   // local exclusive
    if (threadIdx.x == SCAN_BLK - 1) d_bsum[blockIdx.x] = sm[SCAN_BLK - 1];
}

__global__ void scan2_k(int nb) {
    __shared__ int sm[128];
    int t = threadIdx.x;
    int v = (t < nb) ? d_bsum[t] : 0;
    sm[t] = v;
    __syncthreads();
    for (int off = 1; off < 128; off <<= 1) {
        int u = (t >= off) ? sm[t - off] : 0;
        __syncthreads();
        sm[t] += u;
        __syncthreads();
    }
    if (t < nb) d_boff[t] = sm[t] - v;               // exclusive
    if (t == nb - 1) d_boff[nb] = sm[t];             // total
}

// ---------------------------------------------------------------------------
__global__ void fill_k(const int* __restrict__ ei, int E, int N) {
    int e = blockIdx.x * blockDim.x + threadIdx.x;
    if (e >= E) return;
    int s = ei[e];
    int d = ei[E + e];
    if ((unsigned)s >= (unsigned)N || (unsigned)d >= (unsigned)N) return;
    int p = d_offsets[d] + d_boff[d >> SCAN_SHIFT] + d_rank[e];
    if ((unsigned)p < (unsigned)E) {
        float nrm = d_dinv[s] * d_dinv[d];
        d_csr[p] = (ull)(unsigned)s | ((ull)__float_as_uint(nrm) << 32);
    }
}

// ---------------------------------------------------------------------------
// Tensor-core GEMM: d_hwh[N,128](fp16) = src[N,128] @ W[128,128].
// fp16 inputs (converted at SMEM fill), fp32 accumulate via
// mma.sync.aligned.m16n8k16.row.col. Block: 128 thr = 4 warps x 16 rows
// = 64 rows, 64-col half. grid = (ceil(N/64), 2).
// SMEM rows padded +8 halves (stride = 16 mod 128 B) -> conflict-free ldmatrix.
// ---------------------------------------------------------------------------
#define WPAD 72    // 64 cols + 8
#define XPAD 136   // 128 cols + 8

__device__ __forceinline__ uint32_t smem_u32(const void* p) {
    return (uint32_t)__cvta_generic_to_shared(p);
}
__device__ __forceinline__ void ldsm_x4(uint32_t& r0, uint32_t& r1,
                                        uint32_t& r2, uint32_t& r3, uint32_t a) {
    asm volatile("ldmatrix.sync.aligned.m8n8.x4.shared.b16 {%0,%1,%2,%3}, [%4];"
                 : "=r"(r0), "=r"(r1), "=r"(r2), "=r"(r3) : "r"(a));
}
__device__ __forceinline__ void ldsm_x2t(uint32_t& r0, uint32_t& r1, uint32_t a) {
    asm volatile("ldmatrix.sync.aligned.m8n8.x2.trans.shared.b16 {%0,%1}, [%2];"
                 : "=r"(r0), "=r"(r1) : "r"(a));
}
__device__ __forceinline__ void mma16816(float* c, uint32_t a0, uint32_t a1,
                                         uint32_t a2, uint32_t a3,
                                         uint32_t b0, uint32_t b1) {
    asm volatile(
        "mma.sync.aligned.m16n8k16.row.col.f32.f16.f16.f32 "
        "{%0,%1,%2,%3}, {%4,%5,%6,%7}, {%8,%9}, {%0,%1,%2,%3};"
        : "+f"(c[0]), "+f"(c[1]), "+f"(c[2]), "+f"(c[3])
        : "r"(a0), "r"(a1), "r"(a2), "r"(a3), "r"(b0), "r"(b1));
}

template <int LAYER>
__global__ void __launch_bounds__(128) gemm_k(const float* __restrict__ A,
                                              const float* __restrict__ Wg, int N) {
    __shared__ __half Ws[128][WPAD];   // [k][c-half]  18.4 KB
    __shared__ __half Xs[64][XPAD];    // [r][k]       17.4 KB

    int tid = threadIdx.x;
    int c0 = blockIdx.y * 64;
    for (int i = tid; i < 128 * 64; i += 128) {
        int k = i >> 6, c = i & 63;
        Ws[k][c] = __float2half(Wg[(size_t)k * 128 + c0 + c]);
    }

    int r0 = blockIdx.x * 64;
    int rows = N - r0; if (rows > 64) rows = 64;
    if (rows <= 0) return;
    const float* src = (LAYER == 0) ? A : (const float*)d_x1;
    for (int i = tid; i < rows * 128; i += 128) {
        int r = i >> 7, c = i & 127;
        Xs[r][c] = __float2half(src[(size_t)(r0 + r) * 128 + c]);
    }
    for (int i = rows * 128 + tid; i < 64 * 128; i += 128)
        Xs[i >> 7][i & 127] = __half(0);
    __syncthreads();

    int warp = tid >> 5, lane = tid & 31;
    int wr = warp * 16;                       // warp's row base within tile

    float acc[8][4];
#pragma unroll
    for (int nt = 0; nt < 8; nt++)
#pragma unroll
        for (int q = 0; q < 4; q++) acc[nt][q] = 0.f;

    // precomputed ldmatrix lane addresses
    int s4 = lane >> 3;                                     // 0..3
    int arow = wr + (s4 & 1) * 8 + (lane & 7);
    int acolb = (s4 >> 1) * 8;
    int brow_in = lane & 15;                                // 0..15

#pragma unroll
    for (int ks = 0; ks < 8; ks++) {
        uint32_t a0, a1, a2, a3;
        ldsm_x4(a0, a1, a2, a3, smem_u32(&Xs[arow][ks * 16 + acolb]));
        uint32_t baddr = smem_u32(&Ws[ks * 16 + brow_in][0]);
#pragma unroll
        for (int nt = 0; nt < 8; nt++) {
            uint32_t b0, b1;
            ldsm_x2t(b0, b1, baddr + nt * 8 * sizeof(__half));
            mma16816(acc[nt], a0, a1, a2, a3, b0, b1);
        }
    }

    // store: c[q] layout — row (lane>>2) [+8 for q>=2], col 2*(lane&3) + (q&1)
    int rlo = r0 + wr + (lane >> 2);
    int cb = c0 + (lane & 3) * 2;
#pragma unroll
    for (int nt = 0; nt < 8; nt++) {
        int c = cb + nt * 8;
        if (rlo < N)
            *(__half2*)&d_hwh[(size_t)rlo * 128 + c] =
                __floats2half2_rn(acc[nt][0], acc[nt][1]);
        if (rlo + 8 < N)
            *(__half2*)&d_hwh[(size_t)(rlo + 8) * 128 + c] =
                __floats2half2_rn(acc[nt][2], acc[nt][3]);
    }
}

// ---------------------------------------------------------------------------
// Aggregation + ReLU + fused max-pool. Node-balanced warp ranges.
// Offsets reconstructed from local scan + block offsets (L1-resident table).
// ---------------------------------------------------------------------------
__device__ __forceinline__ void pool_flush(float* pool, int g, int pool_off,
                                           int lane, float4 m) {
    unsigned* p = (unsigned*)(pool + (size_t)g * (2 * DIM) + pool_off + lane * 4);
    atomicMax(p + 0, __float_as_uint(m.x));
    atomicMax(p + 1, __float_as_uint(m.y));
    atomicMax(p + 2, __float_as_uint(m.z));
    atomicMax(p + 3, __float_as_uint(m.w));
}

__device__ __forceinline__ void fma_h4(float4& acc, uint2 u, float n) {
    float2 a = __half22float2(*(__half2*)&u.x);
    float2 b = __half22float2(*(__half2*)&u.y);
    acc.x = fmaf(n, a.x, acc.x); acc.y = fmaf(n, a.y, acc.y);
    acc.z = fmaf(n, b.x, acc.z); acc.w = fmaf(n, b.y, acc.w);
}

__device__ __forceinline__ int glob_off(int i, int N, int nb) {
    if (i >= N) return d_boff[nb];
    return d_offsets[i] + d_boff[i >> SCAN_SHIFT];
}

template <int LAYER>
__global__ void __launch_bounds__(256) agg_k(const int* __restrict__ batch,
                                             float* __restrict__ pool, int N, int nb) {
    int warp = threadIdx.x >> 5, lane = threadIdx.x & 31;
    int gw = blockIdx.x * (blockDim.x >> 5) + warp;
    int warpsTotal = gridDim.x * (blockDim.x >> 5);
    int npw = (N + warpsTotal - 1) / warpsTotal;
    int i0 = gw * npw;
    if (i0 >= N) return;
    int i1 = i0 + npw; if (i1 > N) i1 = N;

    const uint2* hwh = (const uint2*)d_hwh;     // 8B = 4 halves per lane
    float4 rmax = make_float4(0.f, 0.f, 0.f, 0.f);
    int curg = -1;
    const int pool_off = (LAYER == 0) ? 0 : DIM;

    int s = glob_off(i0, N, nb);
    for (int i = i0; i < i1; i++) {
        float di = d_dinv[i];
        float sl = di * di;
        float4 acc = make_float4(0.f, 0.f, 0.f, 0.f);
        fma_h4(acc, hwh[(size_t)i * 32 + lane], sl);

        int e = glob_off(i + 1, N, nb);
        int j = s;

        for (; j + 8 <= e; j += 8) {
            ull pk[8];
#pragma unroll
            for (int t = 0; t < 8; t++) pk[t] = d_csr[j + t];
            uint2 v[8];
#pragma unroll
            for (int t = 0; t < 8; t++)
                v[t] = hwh[(size_t)(unsigned)(int)pk[t] * 32 + lane];
#pragma unroll
            for (int t = 0; t < 8; t++)
                fma_h4(acc, v[t], __uint_as_float((unsigned)(pk[t] >> 32)));
        }
        if (j + 4 <= e) {
            ull pk[4];
#pragma unroll
            for (int t = 0; t < 4; t++) pk[t] = d_csr[j + t];
            uint2 v[4];
#pragma unroll
            for (int t = 0; t < 4; t++)
                v[t] = hwh[(size_t)(unsigned)(int)pk[t] * 32 + lane];
#pragma unroll
            for (int t = 0; t < 4; t++)
                fma_h4(acc, v[t], __uint_as_float((unsigned)(pk[t] >> 32)));
            j += 4;
        }
        for (; j < e; j++) {
            ull pk = d_csr[j];
            uint2 v = hwh[(size_t)(unsigned)(int)pk * 32 + lane];
            fma_h4(acc, v, __uint_as_float((unsigned)(pk >> 32)));
        }
        s = e;

        acc.x = fmaxf(acc.x, 0.f); acc.y = fmaxf(acc.y, 0.f);
        acc.z = fmaxf(acc.z, 0.f); acc.w = fmaxf(acc.w, 0.f);

        if (LAYER == 0)
            ((float4*)d_x1)[(size_t)i * 32 + lane] = acc;

        int g = batch[i];
        if ((unsigned)g >= (unsigned)NGRAPH) g = 0;   // guard
        if (g != curg) {
            if (curg >= 0) pool_flush(pool, curg, pool_off, lane, rmax);
            curg = g;
            rmax = acc;
        } else {
            rmax.x = fmaxf(rmax.x, acc.x); rmax.y = fmaxf(rmax.y, acc.y);
            rmax.z = fmaxf(rmax.z, acc.z); rmax.w = fmaxf(rmax.w, acc.w);
        }
    }
    if (curg >= 0) pool_flush(pool, curg, pool_off, lane, rmax);
}

// ---------------------------------------------------------------------------
extern "C" void kernel_launch(void* const* d_in, const int* in_sizes, int n_in,
                              void* d_out, int out_size) {
    const float* x     = (const float*)d_in[0];
    const int*   ei    = (const int*)d_in[1];     // int64 inputs delivered as int32
    const int*   batch = (const int*)d_in[2];
    const float* W1    = (const float*)d_in[3];
    const float* W2    = (const float*)d_in[4];
    float* out = (float*)d_out;

    int N = in_sizes[2];       // 50000
    int E = in_sizes[1] / 2;   // 800000
    int nb = (N + SCAN_BLK - 1) / SCAN_BLK;

    static cudaStream_t s1 = [] {
        cudaStream_t s; cudaStreamCreateWithFlags(&s, cudaStreamNonBlocking); return s;
    }();
    static cudaEvent_t evFork = [] {
        cudaEvent_t e; cudaEventCreateWithFlags(&e, cudaEventDisableTiming); return e;
    }();
    static cudaEvent_t evG0 = [] {
        cudaEvent_t e; cudaEventCreateWithFlags(&e, cudaEventDisableTiming); return e;
    }();

    int gemmBlocks = (N + 63) / 64;
    int aggWarps   = (N + 7) / 8;
    int aggBlocks  = (aggWarps + 7) / 8;

    // --- fork: gemm0 concurrent with the CSR build ---
    cudaEventRecord(evFork, 0);
    cudaStreamWaitEvent(s1, evFork, 0);
    gemm_k<0><<<dim3(gemmBlocks, 2), 128, 0, s1>>>(x, W1, N);
    cudaEventRecord(evG0, s1);

    // --- setup chain on the main stream ---
    int initN = N > NGRAPH * 2 * DIM ? N : NGRAPH * 2 * DIM;
    init_k<<<(initN + 255) / 256, 256>>>(out, N);
    count_k<<<(E + 255) / 256, 256>>>(ei, E, N);
    scan1_k<<<nb, SCAN_BLK>>>(N);
    scan2_k<<<1, 128>>>(nb);
    fill_k<<<(E + 255) / 256, 256>>>(ei, E, N);

    // --- join, then serial core ---
    cudaStreamWaitEvent(0, evG0, 0);
    agg_k<0><<<aggBlocks, 256>>>(batch, out, N, nb);
    gemm_k<1><<<dim3(gemmBlocks, 2), 128>>>(nullptr, W2, N);
    agg_k<1><<<aggBlocks, 256>>>(batch, out, N, nb);
}